// round 11
// baseline (speedup 1.0000x reference)
#include <cuda_runtime.h>
#include <cuda_bf16.h>
#include <mma.h>
#include <stdint.h>

using namespace nvcuda;

// Problem constants (fixed benchmark): N=1e6, IN_C=OUT_C=64, FEAT_C=128, G=4096
#define N_MAX 1000000
#define G_MAX 4096

__device__ int      d_count[G_MAX];
__device__ int      d_offsets[G_MAX + 1];
__device__ int      d_rank[N_MAX];
__device__ int      d_order[N_MAX];
__device__ float    d_mu[G_MAX * 64];
__device__ float    d_sig[G_MAX * 64];
// bf16 hi/lo images of W_fc [64k][64n], packed as bf16-pairs along n: [k][32] u32
__device__ uint32_t d_Wh32[2048];
__device__ uint32_t d_Wl32[2048];

// ---------------------------------------------------------------------------
// Preprocessing
// ---------------------------------------------------------------------------
// mu/sig GEMMs + d_count zeroing + W bf16 hi/lo prep
__global__ void musig_init_kernel(const float* __restrict__ feat,
                                  const float* __restrict__ Wmu, const float* __restrict__ bmu,
                                  const float* __restrict__ Wsg, const float* __restrict__ bsg,
                                  const float* __restrict__ Wfc, int G) {
    int gid = blockIdx.x * blockDim.x + threadIdx.x;
    if (gid < G) d_count[gid] = 0;
    if (gid < 2048) {  // pair (k, 2j)/(k, 2j+1)
        int k = gid >> 5, j = gid & 31;
        float w0 = Wfc[k * 64 + 2 * j];
        float w1 = Wfc[k * 64 + 2 * j + 1];
        __nv_bfloat16 h0 = __float2bfloat16(w0);
        __nv_bfloat16 h1 = __float2bfloat16(w1);
        __nv_bfloat16 l0 = __float2bfloat16(w0 - __bfloat162float(h0));
        __nv_bfloat16 l1 = __float2bfloat16(w1 - __bfloat162float(h1));
        d_Wh32[gid] = (uint32_t)__bfloat16_as_ushort(h0) | ((uint32_t)__bfloat16_as_ushort(h1) << 16);
        d_Wl32[gid] = (uint32_t)__bfloat16_as_ushort(l0) | ((uint32_t)__bfloat16_as_ushort(l1) << 16);
    }

    __shared__ float sF[4][128];
    int t  = threadIdx.x;
    int g0 = blockIdx.x * 4;
    for (int i = t; i < 512; i += 256) {
        int gl = i >> 7, k = i & 127;
        int g  = g0 + gl;
        sF[gl][k] = (g < G) ? feat[(size_t)g * 128 + k] : 0.f;
    }
    __syncthreads();
    int gl = t >> 6, c = t & 63;
    int g  = g0 + gl;
    if (g >= G) return;
    float am = bmu[c], as = bsg[c];
#pragma unroll 4
    for (int k = 0; k < 128; k++) {
        float f = sF[gl][k];
        am = fmaf(f, Wmu[k * 64 + c], am);
        as = fmaf(f, Wsg[k * 64 + c], as);
    }
    d_mu[(size_t)g * 64 + c]  = am;
    d_sig[(size_t)g * 64 + c] = as;
}

// histogram; atomic's return value IS the row's rank within its group
__global__ void hist_kernel(const int* __restrict__ seg, int n) {
    int i = blockIdx.x * blockDim.x + threadIdx.x;
    int base = i * 4;
    if (base + 3 < n) {
        int4 s = *reinterpret_cast<const int4*>(seg + base);
        int r0 = atomicAdd(&d_count[s.x], 1);
        int r1 = atomicAdd(&d_count[s.y], 1);
        int r2 = atomicAdd(&d_count[s.z], 1);
        int r3 = atomicAdd(&d_count[s.w], 1);
        *reinterpret_cast<int4*>(d_rank + base) = make_int4(r0, r1, r2, r3);
    } else {
        for (int j = base; j < n; j++)
            d_rank[j] = atomicAdd(&d_count[seg[j]], 1);
    }
}

__global__ void scan_kernel(int G) {
    __shared__ int wsum[32];
    __shared__ int wpre[32];
    const unsigned full = 0xffffffffu;
    int t = threadIdx.x, lane = t & 31, w = t >> 5;
    int v[4];
    int s = 0;
#pragma unroll
    for (int i = 0; i < 4; i++) {
        int g = 4 * t + i;
        v[i] = (g < G) ? d_count[g] : 0;
        s += v[i];
    }
    int sc = s;
#pragma unroll
    for (int off = 1; off < 32; off <<= 1) {
        int o = __shfl_up_sync(full, sc, off);
        if (lane >= off) sc += o;
    }
    if (lane == 31) wsum[w] = sc;
    __syncthreads();
    if (w == 0) {
        int ws = wsum[lane];
        int p = ws;
#pragma unroll
        for (int off = 1; off < 32; off <<= 1) {
            int o = __shfl_up_sync(full, p, off);
            if (lane >= off) p += o;
        }
        wpre[lane] = p - ws;
    }
    __syncthreads();
    int excl = wpre[w] + sc - s;
#pragma unroll
    for (int i = 0; i < 4; i++) {
        int g = 4 * t + i;
        if (g < G) {
            d_offsets[g] = excl;
            excl += v[i];
        }
    }
    if (t == 1023) d_offsets[G] = excl;
}

// no atomic: position = group offset + precomputed rank
__global__ void scatter_kernel(const int* __restrict__ seg, int n) {
    int i = blockIdx.x * blockDim.x + threadIdx.x;
    int base = i * 4;
    if (base + 3 < n) {
        int4 s = *reinterpret_cast<const int4*>(seg + base);
        int4 r = *reinterpret_cast<const int4*>(d_rank + base);
        d_order[d_offsets[s.x] + r.x] = base;
        d_order[d_offsets[s.y] + r.y] = base + 1;
        d_order[d_offsets[s.z] + r.z] = base + 2;
        d_order[d_offsets[s.w] + r.w] = base + 3;
    } else {
        for (int j = base; j < n; j++)
            d_order[d_offsets[seg[j]] + d_rank[j]] = j;
    }
}

// ---------------------------------------------------------------------------
// Group kernel: wmma bf16 3-split GEMM (HMMA) + fused AdaIN.
//   256 threads (8 warps). Chunk = 128 rows. b_fc cancels after normalization,
//   so D = x @ W only. x staged as bf16 hi/lo (stride 72), W hi/lo (stride 72).
//   Warp w computes output tile rows 16w..16w+15, all 4 col tiles; accumulates
//   3 splits (xh*Wh + xh*Wl + xl*Wh) in fp32 fragments; stores to padded fp32
//   h-cache sH (384 rows, stride 72). Stats read from sH (padded rows are 0).
// SMEM layout (bytes):
//   0      : stats  sSum/sSq/sScale/sShift (4*64 floats = 1KB)
//   1024   : Wh  64*72 bf16 (9216)
//   10240  : Wl  (9216)
//   19456  : Ah  2 bufs * 128*72 bf16 (2*18432)
//   56320  : Al  2 bufs * 18432
//   93184  : sH  384*72 f32 (110592)
//   total 203776
// ---------------------------------------------------------------------------
#define LDA   72
#define CHUNK 128
#define HCAP  384
#define SM_WH 1024
#define SM_WL 10240
#define SM_AH 19456
#define SM_AL 56320
#define SM_H  93184
#define ABUF  18432
#define SMEM_BYTES 203776

typedef wmma::fragment<wmma::matrix_a, 16, 16, 16, __nv_bfloat16, wmma::row_major> FragA;
typedef wmma::fragment<wmma::matrix_b, 16, 16, 16, __nv_bfloat16, wmma::row_major> FragB;
typedef wmma::fragment<wmma::accumulator, 16, 16, 16, float> FragC;

// thread t: row sr = t>>1 (0..127), half sq = t&1 (32 cols)
__device__ __forceinline__ void ldg_rows(const float* __restrict__ x, int off,
                                         int base, int cnt, int sr, int sq,
                                         float4 v[8]) {
    int gr = base + sr;
    if (gr < cnt) {
        int gi = __ldg(&d_order[off + gr]);
        const float4* xr = reinterpret_cast<const float4*>(x + (size_t)gi * 64 + 32 * sq);
#pragma unroll
        for (int i = 0; i < 8; i++) v[i] = xr[i];
    } else {
#pragma unroll
        for (int i = 0; i < 8; i++) v[i] = make_float4(0.f, 0.f, 0.f, 0.f);
    }
}

__device__ __forceinline__ void cvt_sts(char* __restrict__ smem, int buf,
                                        int sr, int sq, const float4 v[8]) {
    uint32_t uh[16], ul[16];
#pragma unroll
    for (int i = 0; i < 8; i++) {
        float f0 = v[i].x, f1 = v[i].y, f2 = v[i].z, f3 = v[i].w;
        __nv_bfloat16 h0 = __float2bfloat16(f0), h1 = __float2bfloat16(f1);
        __nv_bfloat16 h2 = __float2bfloat16(f2), h3 = __float2bfloat16(f3);
        __nv_bfloat16 l0 = __float2bfloat16(f0 - __bfloat162float(h0));
        __nv_bfloat16 l1 = __float2bfloat16(f1 - __bfloat162float(h1));
        __nv_bfloat16 l2 = __float2bfloat16(f2 - __bfloat162float(h2));
        __nv_bfloat16 l3 = __float2bfloat16(f3 - __bfloat162float(h3));
        uh[2 * i]     = (uint32_t)__bfloat16_as_ushort(h0) | ((uint32_t)__bfloat16_as_ushort(h1) << 16);
        uh[2 * i + 1] = (uint32_t)__bfloat16_as_ushort(h2) | ((uint32_t)__bfloat16_as_ushort(h3) << 16);
        ul[2 * i]     = (uint32_t)__bfloat16_as_ushort(l0) | ((uint32_t)__bfloat16_as_ushort(l1) << 16);
        ul[2 * i + 1] = (uint32_t)__bfloat16_as_ushort(l2) | ((uint32_t)__bfloat16_as_ushort(l3) << 16);
    }
    int b2 = sr * (LDA * 2) + 64 * sq;   // byte offset within buffer
    char* Ah = smem + SM_AH + buf * ABUF + b2;
    char* Al = smem + SM_AL + buf * ABUF + b2;
#pragma unroll
    for (int i = 0; i < 4; i++) {
        *reinterpret_cast<uint4*>(Ah + 16 * i) =
            make_uint4(uh[4 * i], uh[4 * i + 1], uh[4 * i + 2], uh[4 * i + 3]);
        *reinterpret_cast<uint4*>(Al + 16 * i) =
            make_uint4(ul[4 * i], ul[4 * i + 1], ul[4 * i + 2], ul[4 * i + 3]);
    }
}

// warp-cooperative: GEMM one 128-row chunk into sH rows [slot, slot+128)
__device__ __forceinline__ void gemm_chunk(char* __restrict__ smem, int buf,
                                           int w, int slot) {
    const __nv_bfloat16* Ah = reinterpret_cast<const __nv_bfloat16*>(smem + SM_AH + buf * ABUF);
    const __nv_bfloat16* Al = reinterpret_cast<const __nv_bfloat16*>(smem + SM_AL + buf * ABUF);
    const __nv_bfloat16* Wh = reinterpret_cast<const __nv_bfloat16*>(smem + SM_WH);
    const __nv_bfloat16* Wl = reinterpret_cast<const __nv_bfloat16*>(smem + SM_WL);
    float* sH = reinterpret_cast<float*>(smem + SM_H);

    FragA a[4];
    FragC acc[4];
#pragma unroll
    for (int ct = 0; ct < 4; ct++) wmma::fill_fragment(acc[ct], 0.f);

#pragma unroll
    for (int s = 0; s < 3; s++) {
        const __nv_bfloat16* A = (s < 2) ? Ah : Al;
        const __nv_bfloat16* B = (s == 1) ? Wl : Wh;
        if (s != 1) {  // s==1 reuses s==0's A fragments
#pragma unroll
            for (int k4 = 0; k4 < 4; k4++)
                wmma::load_matrix_sync(a[k4], A + (size_t)(16 * w) * LDA + 16 * k4, LDA);
        }
#pragma unroll
        for (int ct = 0; ct < 4; ct++) {
#pragma unroll
            for (int k4 = 0; k4 < 4; k4++) {
                FragB b;
                wmma::load_matrix_sync(b, B + (size_t)(16 * k4) * LDA + 16 * ct, LDA);
                wmma::mma_sync(acc[ct], a[k4], b, acc[ct]);
            }
        }
    }
#pragma unroll
    for (int ct = 0; ct < 4; ct++)
        wmma::store_matrix_sync(sH + (size_t)(slot + 16 * w) * LDA + 16 * ct, acc[ct],
                                LDA, wmma::mem_row_major);
}

// stats over chunk at sH slot: thread (rb=t>>4, cb=t&15) reads 8 rows x 4 cols
__device__ __forceinline__ void stats_chunk(const float* __restrict__ sH, int slot,
                                            int rb, int cb,
                                            float csum[4], float csq[4]) {
#pragma unroll
    for (int r8 = 0; r8 < 8; r8++) {
        const float4 hv = *reinterpret_cast<const float4*>(
            sH + (size_t)(slot + rb * 8 + r8) * LDA + 4 * cb);
        csum[0] += hv.x; csq[0] = fmaf(hv.x, hv.x, csq[0]);
        csum[1] += hv.y; csq[1] = fmaf(hv.y, hv.y, csq[1]);
        csum[2] += hv.z; csq[2] = fmaf(hv.z, hv.z, csq[2]);
        csum[3] += hv.w; csq[3] = fmaf(hv.w, hv.w, csq[3]);
    }
}

__global__ __launch_bounds__(256, 1) void group_kernel(const float* __restrict__ x,
                                                       float* __restrict__ out) {
    extern __shared__ char smem[];
    float* sSum   = reinterpret_cast<float*>(smem);
    float* sSq    = sSum + 64;
    float* sScale = sSq + 64;
    float* sShift = sScale + 64;
    float* sH     = reinterpret_cast<float*>(smem + SM_H);

    int t = threadIdx.x, w = t >> 5;
    int g   = blockIdx.x;
    int off = d_offsets[g];
    int cnt = d_offsets[g + 1] - off;
    if (cnt == 0) return;

    // copy W hi/lo into padded smem (stride 72 bf16)
    for (int i = t; i < 2048; i += 256) {
        int k = i >> 5, j = i & 31;
        int b2 = k * (LDA * 2) + 4 * j;
        *reinterpret_cast<uint32_t*>(smem + SM_WH + b2) = d_Wh32[i];
        *reinterpret_cast<uint32_t*>(smem + SM_WL + b2) = d_Wl32[i];
    }
    if (t < 64) { sSum[t] = 0.f; sSq[t] = 0.f; }

    int nch  = (cnt + CHUNK - 1) >> 7;
    bool cached = (cnt <= HCAP);
    int  sr = t >> 1, sq = t & 1;     // staging coords
    int  rb = t >> 4, cb = t & 15;    // stats coords

    float csum[4] = {0.f, 0.f, 0.f, 0.f};
    float csq[4]  = {0.f, 0.f, 0.f, 0.f};
    float4 pv[8];

    // ---------------- pass 1: GEMM + stats ----------------
    if (cached) {
        ldg_rows(x, off, 0, cnt, sr, sq, pv);
        cvt_sts(smem, 0, sr, sq, pv);
        __syncthreads();
        for (int c = 0; c < nch; c++) {
            int slot = c << 7;
            bool havnext = (c + 1 < nch);
            if (havnext) ldg_rows(x, off, slot + CHUNK, cnt, sr, sq, pv);  // LDG in flight
            gemm_chunk(smem, c & 1, w, slot);
            if (havnext) cvt_sts(smem, (c + 1) & 1, sr, sq, pv);
            __syncthreads();           // sH tiles + next A buffer visible
            stats_chunk(sH, slot, rb, cb, csum, csq);
        }
    } else {
        // rare giant group: stats-only pass, sH slot 0 reused
        for (int c = 0; c < nch; c++) {
            ldg_rows(x, off, c << 7, cnt, sr, sq, pv);
            cvt_sts(smem, 0, sr, sq, pv);
            __syncthreads();
            gemm_chunk(smem, 0, w, 0);
            __syncthreads();
            stats_chunk(sH, 0, rb, cb, csum, csq);
            __syncthreads();            // stats done before next overwrite
        }
    }

    // ---------------- reduce stats ----------------
    const unsigned full = 0xffffffffu;
#pragma unroll
    for (int j = 0; j < 4; j++) {
        csum[j] += __shfl_down_sync(full, csum[j], 16);
        csq[j]  += __shfl_down_sync(full, csq[j], 16);
    }
    if ((t & 31) < 16) {
#pragma unroll
        for (int j = 0; j < 4; j++) {
            atomicAdd(&sSum[cb * 4 + j], csum[j]);
            atomicAdd(&sSq[cb * 4 + j],  csq[j]);
        }
    }
    __syncthreads();
    if (t < 64) {
        float inv  = 1.0f / (float)cnt;
        float mean = sSum[t] * inv;
        float var  = fmaxf(sSq[t] * inv - mean * mean, 0.f);
        float sc   = __ldg(&d_sig[(size_t)g * 64 + t]) * rsqrtf(var + 1e-14f);
        sScale[t] = sc;
        sShift[t] = __ldg(&d_mu[(size_t)g * 64 + t]) - mean * sc;
    }
    __syncthreads();

    // ---------------- pass 2: apply + write ----------------
    int lane = t & 31;
    float2 sc2 = reinterpret_cast<float2*>(sScale)[lane];
    float2 sh2 = reinterpret_cast<float2*>(sShift)[lane];
    if (cached) {
        for (int j = w; j < cnt; j += 8) {
            int gi = __ldg(&d_order[off + j]);
            float2 h2 = *reinterpret_cast<float2*>(&sH[(size_t)j * LDA + 2 * lane]);
            float2 o;
            o.x = fmaxf(fmaf(h2.x, sc2.x, sh2.x), 0.f);
            o.y = fmaxf(fmaf(h2.y, sc2.y, sh2.y), 0.f);
            reinterpret_cast<float2*>(out + (size_t)gi * 64)[lane] = o;
        }
    } else {
        // recompute per chunk, apply from sH slot 0
        for (int c = 0; c < nch; c++) {
            int base = c << 7;
            ldg_rows(x, off, base, cnt, sr, sq, pv);
            cvt_sts(smem, 0, sr, sq, pv);
            __syncthreads();
            gemm_chunk(smem, 0, w, 0);
            __syncthreads();
            for (int j = w; j < CHUNK; j += 8) {
                int gr = base + j;
                if (gr < cnt) {
                    int gi = __ldg(&d_order[off + gr]);
                    float2 h2 = *reinterpret_cast<float2*>(&sH[(size_t)j * LDA + 2 * lane]);
                    float2 o;
                    o.x = fmaxf(fmaf(h2.x, sc2.x, sh2.x), 0.f);
                    o.y = fmaxf(fmaf(h2.y, sc2.y, sh2.y), 0.f);
                    reinterpret_cast<float2*>(out + (size_t)gi * 64)[lane] = o;
                }
            }
            __syncthreads();
        }
    }
}

// ---------------------------------------------------------------------------
extern "C" void kernel_launch(void* const* d_in, const int* in_sizes, int n_in,
                              void* d_out, int out_size) {
    int wi = (n_in >= 10) ? 4 : 3;
    const float* x    = (const float*)d_in[0];
    const float* feat = (const float*)d_in[1];
    const int*   seg  = (const int*)d_in[2];
    const float* Wfc  = (const float*)d_in[wi + 0];
    const float* Wmu  = (const float*)d_in[wi + 2];
    const float* bmu  = (const float*)d_in[wi + 3];
    const float* Wsg  = (const float*)d_in[wi + 4];
    const float* bsg  = (const float*)d_in[wi + 5];
    float* out = (float*)d_out;

    int n = in_sizes[0] / 64;
    int G = in_sizes[1] / 128;

    cudaFuncSetAttribute(group_kernel, cudaFuncAttributeMaxDynamicSharedMemorySize,
                         SMEM_BYTES);

    int q = (n + 3) / 4;
    musig_init_kernel<<<(G + 3) / 4, 256>>>(feat, Wmu, bmu, Wsg, bsg, Wfc, G);
    hist_kernel<<<(q + 255) / 256, 256>>>(seg, n);
    scan_kernel<<<1, 1024>>>(G);
    scatter_kernel<<<(q + 255) / 256, 256>>>(seg, n);
    group_kernel<<<G, 256, SMEM_BYTES>>>(x, out);
}

// round 12
// speedup vs baseline: 1.0786x; 1.0786x over previous
#include <cuda_runtime.h>
#include <cuda_bf16.h>
#include <mma.h>
#include <stdint.h>

using namespace nvcuda;

// Problem constants (fixed benchmark): N=1e6, IN_C=OUT_C=64, FEAT_C=128, G=4096
#define N_MAX 1000000
#define G_MAX 4096

__device__ int      d_count[G_MAX];
__device__ int      d_offsets[G_MAX + 1];
__device__ int      d_rank[N_MAX];
__device__ int      d_order[N_MAX];
__device__ float    d_mu[G_MAX * 64];
__device__ float    d_sig[G_MAX * 64];
// bf16 hi/lo images of W_fc [64k][64n], packed as bf16-pairs along n: [k][32] u32
__device__ uint32_t d_Wh32[2048];
__device__ uint32_t d_Wl32[2048];

// ---------------------------------------------------------------------------
// Preprocessing
// ---------------------------------------------------------------------------
__global__ void musig_init_kernel(const float* __restrict__ feat,
                                  const float* __restrict__ Wmu, const float* __restrict__ bmu,
                                  const float* __restrict__ Wsg, const float* __restrict__ bsg,
                                  const float* __restrict__ Wfc, int G) {
    int gid = blockIdx.x * blockDim.x + threadIdx.x;
    if (gid < G) d_count[gid] = 0;
    if (gid < 2048) {  // pair (k, 2j)/(k, 2j+1)
        int k = gid >> 5, j = gid & 31;
        float w0 = Wfc[k * 64 + 2 * j];
        float w1 = Wfc[k * 64 + 2 * j + 1];
        __nv_bfloat16 h0 = __float2bfloat16(w0);
        __nv_bfloat16 h1 = __float2bfloat16(w1);
        __nv_bfloat16 l0 = __float2bfloat16(w0 - __bfloat162float(h0));
        __nv_bfloat16 l1 = __float2bfloat16(w1 - __bfloat162float(h1));
        d_Wh32[gid] = (uint32_t)__bfloat16_as_ushort(h0) | ((uint32_t)__bfloat16_as_ushort(h1) << 16);
        d_Wl32[gid] = (uint32_t)__bfloat16_as_ushort(l0) | ((uint32_t)__bfloat16_as_ushort(l1) << 16);
    }

    __shared__ float sF[4][128];
    int t  = threadIdx.x;
    int g0 = blockIdx.x * 4;
    for (int i = t; i < 512; i += 256) {
        int gl = i >> 7, k = i & 127;
        int g  = g0 + gl;
        sF[gl][k] = (g < G) ? feat[(size_t)g * 128 + k] : 0.f;
    }
    __syncthreads();
    int gl = t >> 6, c = t & 63;
    int g  = g0 + gl;
    if (g >= G) return;
    float am = bmu[c], as = bsg[c];
#pragma unroll 4
    for (int k = 0; k < 128; k++) {
        float f = sF[gl][k];
        am = fmaf(f, Wmu[k * 64 + c], am);
        as = fmaf(f, Wsg[k * 64 + c], as);
    }
    d_mu[(size_t)g * 64 + c]  = am;
    d_sig[(size_t)g * 64 + c] = as;
}

// histogram; atomic's return value IS the row's rank within its group
__global__ void hist_kernel(const int* __restrict__ seg, int n) {
    int i = blockIdx.x * blockDim.x + threadIdx.x;
    int base = i * 4;
    if (base + 3 < n) {
        int4 s = *reinterpret_cast<const int4*>(seg + base);
        int r0 = atomicAdd(&d_count[s.x], 1);
        int r1 = atomicAdd(&d_count[s.y], 1);
        int r2 = atomicAdd(&d_count[s.z], 1);
        int r3 = atomicAdd(&d_count[s.w], 1);
        *reinterpret_cast<int4*>(d_rank + base) = make_int4(r0, r1, r2, r3);
    } else {
        for (int j = base; j < n; j++)
            d_rank[j] = atomicAdd(&d_count[seg[j]], 1);
    }
}

__global__ void scan_kernel(int G) {
    __shared__ int wsum[32];
    __shared__ int wpre[32];
    const unsigned full = 0xffffffffu;
    int t = threadIdx.x, lane = t & 31, w = t >> 5;
    int v[4];
    int s = 0;
#pragma unroll
    for (int i = 0; i < 4; i++) {
        int g = 4 * t + i;
        v[i] = (g < G) ? d_count[g] : 0;
        s += v[i];
    }
    int sc = s;
#pragma unroll
    for (int off = 1; off < 32; off <<= 1) {
        int o = __shfl_up_sync(full, sc, off);
        if (lane >= off) sc += o;
    }
    if (lane == 31) wsum[w] = sc;
    __syncthreads();
    if (w == 0) {
        int ws = wsum[lane];
        int p = ws;
#pragma unroll
        for (int off = 1; off < 32; off <<= 1) {
            int o = __shfl_up_sync(full, p, off);
            if (lane >= off) p += o;
        }
        wpre[lane] = p - ws;
    }
    __syncthreads();
    int excl = wpre[w] + sc - s;
#pragma unroll
    for (int i = 0; i < 4; i++) {
        int g = 4 * t + i;
        if (g < G) {
            d_offsets[g] = excl;
            excl += v[i];
        }
    }
    if (t == 1023) d_offsets[G] = excl;
}

// no atomic: position = group offset + precomputed rank
__global__ void scatter_kernel(const int* __restrict__ seg, int n) {
    int i = blockIdx.x * blockDim.x + threadIdx.x;
    int base = i * 4;
    if (base + 3 < n) {
        int4 s = *reinterpret_cast<const int4*>(seg + base);
        int4 r = *reinterpret_cast<const int4*>(d_rank + base);
        d_order[d_offsets[s.x] + r.x] = base;
        d_order[d_offsets[s.y] + r.y] = base + 1;
        d_order[d_offsets[s.z] + r.z] = base + 2;
        d_order[d_offsets[s.w] + r.w] = base + 3;
    } else {
        for (int j = base; j < n; j++)
            d_order[d_offsets[seg[j]] + d_rank[j]] = j;
    }
}

// ---------------------------------------------------------------------------
// Group kernel: wmma bf16 3-split GEMM + fused AdaIN — 512 threads (16 warps),
// WHOLE group staged once (CAP=320 rows), single GEMM/stats/apply phase,
// ~4 barriers per CTA. b_fc cancels after normalization -> D = x @ W only.
// SMEM (bytes):
//   0      : stats  sSum/sSq/sScale/sShift (1KB)
//   1024   : Wh  64*72 bf16  (9216)
//   10240  : Wl  (9216)
//   19456  : Ah  320*72 bf16 (46080)
//   65536  : Al  (46080)
//   111616 : sH  320*72 f32  (92160)   total 203776
// ---------------------------------------------------------------------------
#define LDA   72
#define HCAP  320
#define SM_WH 1024
#define SM_WL 10240
#define SM_AH 19456
#define SM_AL 65536
#define SM_H  111616
#define SMEM_BYTES 203776
#define NTHREADS 512

typedef wmma::fragment<wmma::matrix_a, 16, 16, 16, __nv_bfloat16, wmma::row_major> FragA;
typedef wmma::fragment<wmma::matrix_b, 16, 16, 16, __nv_bfloat16, wmma::row_major> FragB;
typedef wmma::fragment<wmma::accumulator, 16, 16, 16, float> FragC;

// stage one row-half into local row slot `sr` of Ah/Al: group row = grow,
// half sq (32 cols). grow >= cnt -> zeros.
__device__ __forceinline__ void stage_half(const float* __restrict__ x,
                                           char* __restrict__ smem,
                                           int off, int grow, int cnt,
                                           int sr, int sq) {
    float4 v[8];
    if (grow < cnt) {
        int gi = __ldg(&d_order[off + grow]);
        const float4* xr = reinterpret_cast<const float4*>(x + (size_t)gi * 64 + 32 * sq);
#pragma unroll
        for (int i = 0; i < 8; i++) v[i] = xr[i];
    } else {
#pragma unroll
        for (int i = 0; i < 8; i++) v[i] = make_float4(0.f, 0.f, 0.f, 0.f);
    }
    uint32_t uh[16], ul[16];
#pragma unroll
    for (int i = 0; i < 8; i++) {
        float f0 = v[i].x, f1 = v[i].y, f2 = v[i].z, f3 = v[i].w;
        __nv_bfloat16 h0 = __float2bfloat16(f0), h1 = __float2bfloat16(f1);
        __nv_bfloat16 h2 = __float2bfloat16(f2), h3 = __float2bfloat16(f3);
        __nv_bfloat16 l0 = __float2bfloat16(f0 - __bfloat162float(h0));
        __nv_bfloat16 l1 = __float2bfloat16(f1 - __bfloat162float(h1));
        __nv_bfloat16 l2 = __float2bfloat16(f2 - __bfloat162float(h2));
        __nv_bfloat16 l3 = __float2bfloat16(f3 - __bfloat162float(h3));
        uh[2 * i]     = (uint32_t)__bfloat16_as_ushort(h0) | ((uint32_t)__bfloat16_as_ushort(h1) << 16);
        uh[2 * i + 1] = (uint32_t)__bfloat16_as_ushort(h2) | ((uint32_t)__bfloat16_as_ushort(h3) << 16);
        ul[2 * i]     = (uint32_t)__bfloat16_as_ushort(l0) | ((uint32_t)__bfloat16_as_ushort(l1) << 16);
        ul[2 * i + 1] = (uint32_t)__bfloat16_as_ushort(l2) | ((uint32_t)__bfloat16_as_ushort(l3) << 16);
    }
    int b2 = sr * (LDA * 2) + 64 * sq;
    char* Ah = smem + SM_AH + b2;
    char* Al = smem + SM_AL + b2;
#pragma unroll
    for (int i = 0; i < 4; i++) {
        *reinterpret_cast<uint4*>(Ah + 16 * i) =
            make_uint4(uh[4 * i], uh[4 * i + 1], uh[4 * i + 2], uh[4 * i + 3]);
        *reinterpret_cast<uint4*>(Al + 16 * i) =
            make_uint4(ul[4 * i], ul[4 * i + 1], ul[4 * i + 2], ul[4 * i + 3]);
    }
}

// one m16 row-tile: 3-split GEMM into sH rows [16*tile, 16*tile+16)
__device__ __forceinline__ void gemm_tile(char* __restrict__ smem, int tile) {
    const __nv_bfloat16* Ah = reinterpret_cast<const __nv_bfloat16*>(smem + SM_AH);
    const __nv_bfloat16* Al = reinterpret_cast<const __nv_bfloat16*>(smem + SM_AL);
    const __nv_bfloat16* Wh = reinterpret_cast<const __nv_bfloat16*>(smem + SM_WH);
    const __nv_bfloat16* Wl = reinterpret_cast<const __nv_bfloat16*>(smem + SM_WL);
    float* sH = reinterpret_cast<float*>(smem + SM_H);

    FragA a[4];
    FragC acc[4];
#pragma unroll
    for (int ct = 0; ct < 4; ct++) wmma::fill_fragment(acc[ct], 0.f);
#pragma unroll
    for (int s = 0; s < 3; s++) {
        const __nv_bfloat16* A = (s < 2) ? Ah : Al;
        const __nv_bfloat16* B = (s == 1) ? Wl : Wh;
        if (s != 1) {  // s==1 reuses s==0's A fragments
#pragma unroll
            for (int k4 = 0; k4 < 4; k4++)
                wmma::load_matrix_sync(a[k4], A + (size_t)(16 * tile) * LDA + 16 * k4, LDA);
        }
#pragma unroll
        for (int ct = 0; ct < 4; ct++) {
#pragma unroll
            for (int k4 = 0; k4 < 4; k4++) {
                FragB b;
                wmma::load_matrix_sync(b, B + (size_t)(16 * k4) * LDA + 16 * ct, LDA);
                wmma::mma_sync(acc[ct], a[k4], b, acc[ct]);
            }
        }
    }
#pragma unroll
    for (int ct = 0; ct < 4; ct++)
        wmma::store_matrix_sync(sH + (size_t)(16 * tile) * LDA + 16 * ct, acc[ct],
                                LDA, wmma::mem_row_major);
}

__global__ __launch_bounds__(NTHREADS, 1) void group_kernel(const float* __restrict__ x,
                                                            float* __restrict__ out) {
    extern __shared__ char smem[];
    float* sSum   = reinterpret_cast<float*>(smem);
    float* sSq    = sSum + 64;
    float* sScale = sSq + 64;
    float* sShift = sScale + 64;
    float* sH     = reinterpret_cast<float*>(smem + SM_H);

    int t = threadIdx.x, w = t >> 5, lane = t & 31;
    int g   = blockIdx.x;
    int off = d_offsets[g];
    int cnt = d_offsets[g + 1] - off;
    if (cnt == 0) return;

    // W hi/lo -> padded smem (stride 72 bf16)
    for (int i = t; i < 2048; i += NTHREADS) {
        int k = i >> 5, j = i & 31;
        int b2 = k * (LDA * 2) + 4 * j;
        *reinterpret_cast<uint32_t*>(smem + SM_WH + b2) = d_Wh32[i];
        *reinterpret_cast<uint32_t*>(smem + SM_WL + b2) = d_Wl32[i];
    }
    if (t < 64) { sSum[t] = 0.f; sSq[t] = 0.f; }

    bool cached = (cnt <= HCAP);
    int  rb = t >> 4, cb = t & 15;    // stats coords
    int  sr = t >> 1, sq = t & 1;     // staging coords
    float csum[4] = {0.f, 0.f, 0.f, 0.f};
    float csq[4]  = {0.f, 0.f, 0.f, 0.f};

    if (cached) {
        int ntiles = (cnt + 15) >> 4;
        int prows  = ntiles << 4;
        // ---- stage whole group (rows >= cnt zero-filled up to prows) ----
        if (sr < prows) stage_half(x, smem, off, sr, cnt, sr, sq);
        if (t < 128 && 256 + sr < prows)
            stage_half(x, smem, off, 256 + sr, cnt, 256 + sr, sq);
        __syncthreads();
        // ---- GEMM all tiles ----
        for (int tile = w; tile < ntiles; tile += 16) gemm_tile(smem, tile);
        __syncthreads();
        // ---- stats from sH (padded rows are exact zeros) ----
        for (int j = rb; j < prows; j += 32) {
            float4 hv = *reinterpret_cast<const float4*>(sH + (size_t)j * LDA + 4 * cb);
            csum[0] += hv.x; csq[0] = fmaf(hv.x, hv.x, csq[0]);
            csum[1] += hv.y; csq[1] = fmaf(hv.y, hv.y, csq[1]);
            csum[2] += hv.z; csq[2] = fmaf(hv.z, hv.z, csq[2]);
            csum[3] += hv.w; csq[3] = fmaf(hv.w, hv.w, csq[3]);
        }
    } else {
        // ---- rare giant group: chunks of 256 rows, stats only ----
        int nch = (cnt + 255) >> 8;
        for (int c = 0; c < nch; c++) {
            int base = c << 8;
            stage_half(x, smem, off, base + sr, cnt, sr, sq);
            __syncthreads();
            gemm_tile(smem, w);          // 16 warps x 1 tile = 256 rows
            __syncthreads();
            for (int j = rb; j < 256; j += 32) {
                float4 hv = *reinterpret_cast<const float4*>(sH + (size_t)j * LDA + 4 * cb);
                csum[0] += hv.x; csq[0] = fmaf(hv.x, hv.x, csq[0]);
                csum[1] += hv.y; csq[1] = fmaf(hv.y, hv.y, csq[1]);
                csum[2] += hv.z; csq[2] = fmaf(hv.z, hv.z, csq[2]);
                csum[3] += hv.w; csq[3] = fmaf(hv.w, hv.w, csq[3]);
            }
            __syncthreads();
        }
    }

    // ---- reduce stats ----
    const unsigned full = 0xffffffffu;
#pragma unroll
    for (int j = 0; j < 4; j++) {
        csum[j] += __shfl_down_sync(full, csum[j], 16);
        csq[j]  += __shfl_down_sync(full, csq[j], 16);
    }
    if (lane < 16) {
#pragma unroll
        for (int j = 0; j < 4; j++) {
            atomicAdd(&sSum[cb * 4 + j], csum[j]);
            atomicAdd(&sSq[cb * 4 + j],  csq[j]);
        }
    }
    __syncthreads();
    if (t < 64) {
        float inv  = 1.0f / (float)cnt;
        float mean = sSum[t] * inv;
        float var  = fmaxf(sSq[t] * inv - mean * mean, 0.f);
        float sc   = __ldg(&d_sig[(size_t)g * 64 + t]) * rsqrtf(var + 1e-14f);
        sScale[t] = sc;
        sShift[t] = __ldg(&d_mu[(size_t)g * 64 + t]) - mean * sc;
    }
    __syncthreads();

    // ---- apply + write ----
    float2 sc2 = reinterpret_cast<float2*>(sScale)[lane];
    float2 sh2 = reinterpret_cast<float2*>(sShift)[lane];
    if (cached) {
        for (int j = w; j < cnt; j += 16) {
            int gi = __ldg(&d_order[off + j]);
            float2 h2 = *reinterpret_cast<float2*>(&sH[(size_t)j * LDA + 2 * lane]);
            float2 o;
            o.x = fmaxf(fmaf(h2.x, sc2.x, sh2.x), 0.f);
            o.y = fmaxf(fmaf(h2.y, sc2.y, sh2.y), 0.f);
            reinterpret_cast<float2*>(out + (size_t)gi * 64)[lane] = o;
        }
    } else {
        int nch = (cnt + 255) >> 8;
        for (int c = 0; c < nch; c++) {
            int base = c << 8;
            stage_half(x, smem, off, base + sr, cnt, sr, sq);
            __syncthreads();
            gemm_tile(smem, w);
            __syncthreads();
            for (int j = w; j < 256; j += 16) {
                int gr = base + j;
                if (gr < cnt) {
                    int gi = __ldg(&d_order[off + gr]);
                    float2 h2 = *reinterpret_cast<float2*>(&sH[(size_t)j * LDA + 2 * lane]);
                    float2 o;
                    o.x = fmaxf(fmaf(h2.x, sc2.x, sh2.x), 0.f);
                    o.y = fmaxf(fmaf(h2.y, sc2.y, sh2.y), 0.f);
                    reinterpret_cast<float2*>(out + (size_t)gi * 64)[lane] = o;
                }
            }
            __syncthreads();
        }
    }
}

// ---------------------------------------------------------------------------
extern "C" void kernel_launch(void* const* d_in, const int* in_sizes, int n_in,
                              void* d_out, int out_size) {
    int wi = (n_in >= 10) ? 4 : 3;
    const float* x    = (const float*)d_in[0];
    const float* feat = (const float*)d_in[1];
    const int*   seg  = (const int*)d_in[2];
    const float* Wfc  = (const float*)d_in[wi + 0];
    const float* Wmu  = (const float*)d_in[wi + 2];
    const float* bmu  = (const float*)d_in[wi + 3];
    const float* Wsg  = (const float*)d_in[wi + 4];
    const float* bsg  = (const float*)d_in[wi + 5];
    float* out = (float*)d_out;

    int n = in_sizes[0] / 64;
    int G = in_sizes[1] / 128;

    cudaFuncSetAttribute(group_kernel, cudaFuncAttributeMaxDynamicSharedMemorySize,
                         SMEM_BYTES);

    int q = (n + 3) / 4;
    musig_init_kernel<<<(G + 3) / 4, 256>>>(feat, Wmu, bmu, Wsg, bsg, Wfc, G);
    hist_kernel<<<(q + 255) / 256, 256>>>(seg, n);
    scan_kernel<<<1, 1024>>>(G);
    scatter_kernel<<<(q + 255) / 256, 256>>>(seg, n);
    group_kernel<<<G, NTHREADS, SMEM_BYTES>>>(x, out);
}